// round 10
// baseline (speedup 1.0000x reference)
#include <cuda_runtime.h>
#include <cuda_fp16.h>
#include <cstdint>

// Sizes (fixed by the problem)
#define BB   32
#define TT   128
#define INN  128
#define HH   256
#define G4   1024   // 4*HH
#define OO   128

// ---------------- scratch (__device__ globals: no runtime allocation) -------
static __device__ __align__(16) float g_xg[BB * TT * G4];   // xg = x@W_ih^T + b_ih + b_hh
static __device__ __align__(16) float g_bx[BB * TT * HH];   // Bx = x@W_B^T + b_B
static __device__ __align__(16) __half g_whh_h[G4 * HH];    // W_hh fp16, 4-way split layout
static __device__ __align__(16) float g_wa_p[HH * HH];      // W_A fp32 repack
static __device__ __align__(16) float g_m2_p[HH * HH];      // M2 = W_A*D*W_A fp32 repack
static __device__ __align__(16) float g_m2f[HH * HH];       // M2 row-major intermediate
static __device__ __align__(16) float g_wc_p[OO * HH];      // W_C fp32 repack

typedef unsigned long long ull;

__device__ __forceinline__ ull ffma2(ull c, ull a, ull b) {
    ull d;
    asm("fma.rn.f32x2 %0, %1, %2, %3;" : "=l"(d) : "l"(a), "l"(b), "l"(c));
    return d;
}
__device__ __forceinline__ float hsum2(ull v) {
    return __uint_as_float((unsigned)(v & 0xffffffffull)) +
           __uint_as_float((unsigned)(v >> 32));
}
__device__ __forceinline__ ull packf2(float x, float y) {
    ull r; asm("mov.b64 %0, {%1, %2};" : "=l"(r) : "f"(x), "f"(y)); return r;
}
__device__ __forceinline__ ull h2f2(unsigned h2bits) {
    __half2 h = *reinterpret_cast<const __half2*>(&h2bits);
    float2 f = __half22float2(h);
    return packf2(f.x, f.y);
}
// 16B L2-only load (protect L1 residency of W_hh)
__device__ __forceinline__ ulonglong2 ldcg16(const void* p) {
    float4 t = __ldcg((const float4*)p);
    ulonglong2 r; r.x = packf2(t.x, t.y); r.y = packf2(t.z, t.w);
    return r;
}
__device__ __forceinline__ uint32_t s2u(const void* p) {
    uint32_t a;
    asm("{ .reg .u64 t; cvta.to.shared.u64 t, %1; cvt.u32.u64 %0, t; }"
        : "=r"(a) : "l"(p));
    return a;
}
__device__ __forceinline__ void stc(uint32_t laddr, unsigned rank, float v) {
    uint32_t r;
    asm volatile("mapa.shared::cluster.u32 %0, %1, %2;" : "=r"(r) : "r"(laddr), "r"(rank));
    asm volatile("st.shared::cluster.f32 [%0], %1;" :: "r"(r), "f"(v) : "memory");
}
__device__ __forceinline__ void arrive_rel(uint32_t lmbar, unsigned rank) {
    uint32_t r;
    asm volatile("mapa.shared::cluster.u32 %0, %1, %2;" : "=r"(r) : "r"(lmbar), "r"(rank));
    asm volatile("mbarrier.arrive.release.cluster.shared::cluster.b64 _, [%0];"
                 :: "r"(r) : "memory");
}
__device__ __forceinline__ void waitp(uint32_t mb, unsigned parity) {
    asm volatile(
        "{\n\t.reg .pred P;\n\t"
        "W1_%=:\n\t"
        "mbarrier.try_wait.parity.acquire.cluster.shared::cta.b64 P, [%0], %1, 0x989680;\n\t"
        "@P bra W2_%=;\n\t"
        "bra W1_%=;\n\t"
        "W2_%=:\n\t}"
        :: "r"(mb), "r"(parity) : "memory");
}
// fast sigmoid / tanh (sat-safe at +-inf, ~1e-6 abs err)
__device__ __forceinline__ float fsig(float x) {
    return __fdividef(1.f, 1.f + __expf(-x));
}
__device__ __forceinline__ float ftanh(float x) {
    float e = __expf(2.f * x);                 // inf ok
    return 1.f - __fdividef(2.f, e + 1.f);     // -> 1 for inf, -1 for 0
}

// ---------------- M2 = W_A * diag(1/tau) * W_A  (fp32, one-time) ------------
__global__ __launch_bounds__(256) void compute_m2(const float* __restrict__ W_A,
                                                  const float* __restrict__ tau)
{
    __shared__ float ai[HH];
    const int i = blockIdx.x, j = threadIdx.x;
    ai[j] = W_A[i * HH + j] / tau[j];
    __syncthreads();
    float acc = 0.f;
    for (int k = 0; k < HH; k++)
        acc += ai[k] * W_A[k * HH + j];
    g_m2f[i * HH + j] = acc;
}

// ---------------- precompute GEMMs: C[4096,N] = X[4096,128] @ W[N,128]^T + bias (+bias2)
template <int N, int DEST>
__global__ __launch_bounds__(256) void gemm_bias(
    const float* __restrict__ X, const float* __restrict__ W,
    const float* __restrict__ bias, const float* __restrict__ bias2)
{
    constexpr int K = INN;  // 128
    __shared__ float As[32][64];
    __shared__ float Bs[32][64];
    float* C = (DEST == 0) ? g_xg : g_bx;

    const int bm = blockIdx.y * 64, bn = blockIdx.x * 64;
    const int tid = threadIdx.x;
    const int tx = tid & 15, ty = tid >> 4;

    float acc[4][4];
#pragma unroll
    for (int r = 0; r < 4; r++)
#pragma unroll
        for (int c = 0; c < 4; c++) acc[r][c] = 0.f;

    for (int k0 = 0; k0 < K; k0 += 32) {
#pragma unroll
        for (int q = 0; q < 2; q++) {
            int i = tid * 2 + q;
            int row = i >> 3;
            int kc = (i & 7) * 4;
            float4 a = *(const float4*)(X + (size_t)(bm + row) * K + k0 + kc);
            As[kc + 0][row] = a.x; As[kc + 1][row] = a.y;
            As[kc + 2][row] = a.z; As[kc + 3][row] = a.w;
            float4 b = *(const float4*)(W + (size_t)(bn + row) * K + k0 + kc);
            Bs[kc + 0][row] = b.x; Bs[kc + 1][row] = b.y;
            Bs[kc + 2][row] = b.z; Bs[kc + 3][row] = b.w;
        }
        __syncthreads();
#pragma unroll
        for (int kk = 0; kk < 32; kk++) {
            float4 av = *(const float4*)&As[kk][ty * 4];
            float4 bv = *(const float4*)&Bs[kk][tx * 4];
            float ar[4] = {av.x, av.y, av.z, av.w};
            float br[4] = {bv.x, bv.y, bv.z, bv.w};
#pragma unroll
            for (int r = 0; r < 4; r++)
#pragma unroll
                for (int c = 0; c < 4; c++) acc[r][c] += ar[r] * br[c];
        }
        __syncthreads();
    }

    float bc[4];
#pragma unroll
    for (int c = 0; c < 4; c++) {
        bc[c] = bias[bn + tx * 4 + c];
        if (bias2) bc[c] += bias2[bn + tx * 4 + c];
    }
#pragma unroll
    for (int r = 0; r < 4; r++) {
        float4 o;
        o.x = acc[r][0] + bc[0]; o.y = acc[r][1] + bc[1];
        o.z = acc[r][2] + bc[2]; o.w = acc[r][3] + bc[3];
        *(float4*)(C + (size_t)(bm + ty * 4 + r) * N + bn + tx * 4) = o;
    }
}

// ---------------- weight repack (layouts as in R9) --------------------------
__global__ void pack_weights(const float* __restrict__ W_hh,
                             const float* __restrict__ W_A,
                             const float* __restrict__ W_C)
{
    int i = blockIdx.x * blockDim.x + threadIdx.x;
    if (i < G4 * HH) {  // fp16 whh
        int m = i & 7; int u = i >> 3;
        int tid = u & 1023; int cj = u >> 10; int j = cj & 7; int c = cj >> 3;
        int rl = tid >> 2, q = tid & 3;
        int gq = rl >> 6, hl = rl & 63;
        int grow = gq * HH + c * 64 + hl;
        g_whh_h[i] = __float2half(W_hh[grow * HH + q * 64 + j * 8 + m]);
    }
    if (i < HH * HH) {
        int m = i & 3; int r = i >> 2;
        int tid = r & 1023; int cj = r >> 10; int j = cj & 3; int c = cj >> 2;
        int rl = tid >> 4, q = tid & 15;
        int src = (c * 64 + rl) * HH + q * 16 + j * 4 + m;
        g_wa_p[i] = W_A[src];
        g_m2_p[i] = g_m2f[src];
    }
    if (i < OO * HH) {
        int m = i & 3; int r = i >> 2;
        int tid = r & 1023; int cj = r >> 10; int j = cj & 1; int c = cj >> 1;
        int rl = tid >> 5, q = tid & 31;
        g_wc_p[i] = W_C[(c * 32 + rl) * HH + q * 8 + j * 4 + m];
    }
}

// ---------------- sequential fused kernel: 4-CTA cluster per batch ----------
__global__ __launch_bounds__(1024, 1) __cluster_dims__(4, 1, 1)
void seq_kernel(const float* __restrict__ timespans,  // [B,T]
                const float* __restrict__ tau,        // [H]
                const float* __restrict__ sigma,      // [H]
                const float* __restrict__ b_C,        // [OUT]
                float* __restrict__ out)              // [B,T,OUT]
{
    __shared__ __align__(16) float ex_h[2][HH];
    __shared__ __align__(16) float ex_u[2][HH];
    __shared__ __align__(16) float ex_us[2][HH];   // u / tau
    __shared__ __align__(16) float ex_fu[2][HH];   // tanh(u / sigma)
    __shared__ __align__(16) float sh_g[256];      // this rank's 256 gate rows
    __shared__ float sh_v1[64], sh_drv[64], sh_v2[64];
    __shared__ __align__(8) unsigned long long mbar[2];

    const int tid = threadIdx.x;
    const unsigned c = blockIdx.x & 3;       // cluster rank
    const int b = blockIdx.x >> 2;           // batch

    if (tid < HH) {
#pragma unroll
        for (int p = 0; p < 2; p++) {
            ex_h[p][tid] = 0.f; ex_u[p][tid] = 0.f;
            ex_us[p][tid] = 0.f; ex_fu[p][tid] = 0.f;
        }
    }
    const uint32_t mb0 = s2u(mbar);
    if (tid == 0) {
        asm volatile("mbarrier.init.shared.b64 [%0], %1;" :: "r"(mb0), "r"(256u) : "memory");
        asm volatile("mbarrier.init.shared.b64 [%0], %1;" :: "r"(mb0 + 8), "r"(256u) : "memory");
    }
    __syncthreads();
    asm volatile("barrier.cluster.arrive.aligned;" ::: "memory");
    asm volatile("barrier.cluster.wait.aligned;" ::: "memory");

    // thread roles
    const int rlA = tid >> 2, qA = tid & 3;          // gate rows: 4 lanes/row
    const int gq = rlA >> 6, hl = rlA & 63;
    const int grow = gq * HH + c * 64 + hl;          // global gate row
    const int rlW = tid >> 4, qW = tid & 15;         // W_A/M2 rows: 16 lanes/row
    const int rlC = tid >> 5, qC = tid & 31;         // W_C rows: 32 lanes/row
    const int iO = tid & 63;                         // ODE h-index (tid<256, 4x redundant)
    const unsigned gO = (unsigned)(tid >> 6);        // publish target rank (tid<256)

    float itau_o = 0.f, isig_o = 0.f, u_reg = 0.f, c_reg = 0.f;
    if (tid < 256) {
        itau_o = 1.f / tau[c * 64 + iO];
        isig_o = 1.f / sigma[c * 64 + iO];
    }
    const float bCr = b_C[c * 32 + rlC];

    const ulonglong2* whh16 = (const ulonglong2*)g_whh_h + (c * 8) * 1024 + tid;
    const float* wap = g_wa_p + ((c * 4) * 1024 + tid) * 4;
    const float* m2p = g_m2_p + ((c * 4) * 1024 + tid) * 4;
    const float* wcp = g_wc_p + ((c * 2) * 1024 + tid) * 4;

    const uint32_t a_h[2]  = { s2u(ex_h[0]),  s2u(ex_h[1])  };
    const uint32_t a_u[2]  = { s2u(ex_u[0]),  s2u(ex_u[1])  };
    const uint32_t a_us[2] = { s2u(ex_us[0]), s2u(ex_us[1]) };
    const uint32_t a_fu[2] = { s2u(ex_fu[0]), s2u(ex_fu[1]) };

    const float* xg_b = g_xg + (size_t)b * TT * G4;
    const float* bx_b = g_bx + (size_t)b * TT * HH;
    const float* ts_b = timespans + b * TT;
    float* out_b = out + (size_t)b * TT * OO;

    for (int t = 0; t < TT; t++) {
        const int p = t & 1, pn = p ^ 1;
        const unsigned par = (unsigned)((t >> 1) & 1);

        // ---- prefetch this step's scalars (L2 latency hidden under Phase A)
        const float ts = ts_b[t];
        const float xg_r = __ldcg(&xg_b[(size_t)t * G4 + grow]);
        float bx_r = 0.f;
        if (tid < 256) bx_r = __ldcg(&bx_b[(size_t)t * HH + c * 64 + iO]);

        // ---- Phase A: 256 gate rows, dot(h_prev, W_hh row) fp16, 4 lanes/row
        {
            const ulonglong2* hh = (const ulonglong2*)&ex_h[p][qA * 64];
            ull a0 = 0ull, a1 = 0ull;
#pragma unroll
            for (int j = 0; j < 8; j++) {
                ulonglong2 wv = whh16[j * 1024];   // L1-resident LDG.128 (8 halves)
                ulonglong2 h0 = hh[2 * j];
                ulonglong2 h1 = hh[2 * j + 1];
                a0 = ffma2(a0, h2f2((unsigned)wv.x),         h0.x);
                a1 = ffma2(a1, h2f2((unsigned)(wv.x >> 32)), h0.y);
                a0 = ffma2(a0, h2f2((unsigned)wv.y),         h1.x);
                a1 = ffma2(a1, h2f2((unsigned)(wv.y >> 32)), h1.y);
            }
            float v = hsum2(a0) + hsum2(a1);
            v += __shfl_down_sync(0xffffffffu, v, 2, 4);
            v += __shfl_down_sync(0xffffffffu, v, 1, 4);
            if (qA == 0) sh_g[rlA] = v + xg_r;
        }

        // ---- Phase A2: v1 = ts*W_A@us, drv = W_A@fu, v2 = ts*M2@us (local)
        {
            const ulonglong2* us2 = (const ulonglong2*)&ex_us[p][qW * 16];
            const ulonglong2* fu2 = (const ulonglong2*)&ex_fu[p][qW * 16];
            ull av = 0ull, ad = 0ull, a2 = 0ull;
#pragma unroll
            for (int j = 0; j < 4; j++) {
                ulonglong2 wv = ldcg16(wap + j * 4096);   // L2-only
                ulonglong2 mv = ldcg16(m2p + j * 4096);   // L2-only
                ulonglong2 uv = us2[j];
                ulonglong2 fv = fu2[j];
                av = ffma2(av, wv.x, uv.x); av = ffma2(av, wv.y, uv.y);
                ad = ffma2(ad, wv.x, fv.x); ad = ffma2(ad, wv.y, fv.y);
                a2 = ffma2(a2, mv.x, uv.x); a2 = ffma2(a2, mv.y, uv.y);
            }
            float v = hsum2(av), d = hsum2(ad), w = hsum2(a2);
#pragma unroll
            for (int o = 8; o >= 1; o >>= 1) {
                v += __shfl_down_sync(0xffffffffu, v, o, 16);
                d += __shfl_down_sync(0xffffffffu, d, o, 16);
                w += __shfl_down_sync(0xffffffffu, w, o, 16);
            }
            if (qW == 0) {
                sh_v1[rlW] = ts * v;
                sh_drv[rlW] = d;
                sh_v2[rlW] = ts * w;     // = A_eff @ v1  (via M2)
            }
        }
        __syncthreads();   // sh_g / sh_v1 / sh_drv / sh_v2 visible CTA-wide

        // ---- LSTM cell + ODE update: tid<256, 4x redundant; each thread
        //      publishes its h-index to ONE rank (gO) -> tail spread over 8 warps
        if (tid < 256) {
            float gi = sh_g[iO], gf = sh_g[64 + iO];
            float gg = sh_g[128 + iO], go = sh_g[192 + iO];
            float si = fsig(gi);
            float sf = fsig(gf);
            float so = fsig(go);
            c_reg = sf * c_reg + si * ftanh(gg);
            float bb = so * ftanh(c_reg);

            float un = u_reg + sh_v1[iO] + 0.5f * ts * sh_v2[iO]
                     + ts * (sh_drv[iO] + bx_r) * itau_o + bb;
            u_reg = un;
            float us = un * itau_o;
            float fu = ftanh(un * isig_o);

            const uint32_t off = (unsigned)(c * 64 + iO) * 4;
            stc(a_u[pn] + off, gO, un);
            stc(a_us[pn] + off, gO, us);
            stc(a_fu[pn] + off, gO, fu);
            stc(a_h[pn] + off, gO, bb);
            arrive_rel(mb0 + (unsigned)p * 8, gO);
        }
        // order ALL local reads (sh_g/sh_v*/ex[p]) before next-step overwrites:
        // publishers no longer all arrive at the local barrier, so this BAR
        // carries the intra-CTA ordering that waitp used to provide.
        __syncthreads();

        waitp(mb0 + (unsigned)p * 8, par);   // full u/us/fu/h of this step available

        // ---- Phase D: y = u_new @ W_C^T + b_C (own 32 rows, 32 lanes/row) --
        {
            const ulonglong2* uu = (const ulonglong2*)&ex_u[pn][qC * 8];
            ull ay = 0ull;
#pragma unroll
            for (int j = 0; j < 2; j++) {
                ulonglong2 wv = ldcg16(wcp + j * 4096);
                ulonglong2 uv = uu[j];
                ay = ffma2(ay, wv.x, uv.x);
                ay = ffma2(ay, wv.y, uv.y);
            }
            float y = hsum2(ay);
#pragma unroll
            for (int o = 16; o >= 1; o >>= 1)
                y += __shfl_down_sync(0xffffffffu, y, o, 32);
            if (qC == 0) out_b[(size_t)t * OO + c * 32 + rlC] = y + bCr;
        }
    }

    // no CTA may exit while peers' remote stores could still target its SMEM
    asm volatile("barrier.cluster.arrive.aligned;" ::: "memory");
    asm volatile("barrier.cluster.wait.aligned;" ::: "memory");
}

// ---------------- launch ----------------------------------------------------
extern "C" void kernel_launch(void* const* d_in, const int* in_sizes, int n_in,
                              void* d_out, int out_size)
{
    const float* x    = (const float*)d_in[0];   // [32,128,128]
    const float* tsp  = (const float*)d_in[1];   // [32,128]
    const float* tau  = (const float*)d_in[2];   // [256]
    const float* sig  = (const float*)d_in[3];   // [256]
    const float* W_A  = (const float*)d_in[4];   // [256,256]
    const float* W_B  = (const float*)d_in[5];   // [256,128]
    const float* b_B  = (const float*)d_in[6];   // [256]
    const float* W_C  = (const float*)d_in[7];   // [128,256]
    const float* b_C  = (const float*)d_in[8];   // [128]
    const float* W_ih = (const float*)d_in[9];   // [1024,128]
    const float* W_hh = (const float*)d_in[10];  // [1024,256]
    const float* b_ih = (const float*)d_in[11];  // [1024]
    const float* b_hh = (const float*)d_in[12];  // [1024]
    float* out = (float*)d_out;                  // [32,128,128]

    // M2 = W_A * diag(1/tau) * W_A, then repack all weights
    compute_m2<<<HH, HH>>>(W_A, tau);
    pack_weights<<<(G4 * HH + 255) / 256, 256>>>(W_hh, W_A, W_C);

    gemm_bias<G4, 0><<<dim3(G4 / 64, (BB * TT) / 64), 256>>>(x, W_ih, b_ih, b_hh);
    gemm_bias<HH, 1><<<dim3(HH / 64, (BB * TT) / 64), 256>>>(x, W_B, b_B, nullptr);

    // 32 batches x 4-CTA clusters = 128 CTAs
    seq_kernel<<<BB * 4, 1024>>>(tsp, tau, sig, b_C, out);
}

// round 11
// speedup vs baseline: 1.0064x; 1.0064x over previous
#include <cuda_runtime.h>
#include <cuda_fp16.h>
#include <cstdint>

// Sizes (fixed by the problem)
#define BB   32
#define TT   128
#define INN  128
#define HH   256
#define G4   1024   // 4*HH
#define OO   128

// ---------------- scratch (__device__ globals: no runtime allocation) -------
static __device__ __align__(16) float g_xg[BB * TT * G4];   // xg = x@W_ih^T + b_ih + b_hh
static __device__ __align__(16) float g_bx[BB * TT * HH];   // Bx = x@W_B^T + b_B
static __device__ __align__(16) __half g_whh_h[G4 * HH];    // W_hh fp16, 4-way split layout
static __device__ __align__(16) float g_wa_p[HH * HH];      // W_A fp32 repack
static __device__ __align__(16) float g_m2_p[HH * HH];      // M2 = W_A*D*W_A fp32 repack
static __device__ __align__(16) float g_m2f[HH * HH];       // M2 row-major intermediate
static __device__ __align__(16) float g_wc_p[OO * HH];      // W_C fp32 repack

typedef unsigned long long ull;

__device__ __forceinline__ ull ffma2(ull c, ull a, ull b) {
    ull d;
    asm("fma.rn.f32x2 %0, %1, %2, %3;" : "=l"(d) : "l"(a), "l"(b), "l"(c));
    return d;
}
__device__ __forceinline__ float hsum2(ull v) {
    return __uint_as_float((unsigned)(v & 0xffffffffull)) +
           __uint_as_float((unsigned)(v >> 32));
}
__device__ __forceinline__ ull packf2(float x, float y) {
    ull r; asm("mov.b64 %0, {%1, %2};" : "=l"(r) : "f"(x), "f"(y)); return r;
}
__device__ __forceinline__ ull h2f2(unsigned h2bits) {
    __half2 h = *reinterpret_cast<const __half2*>(&h2bits);
    float2 f = __half22float2(h);
    return packf2(f.x, f.y);
}
// 16B L2-only load (protect L1 residency of W_hh)
__device__ __forceinline__ ulonglong2 ldcg16(const void* p) {
    float4 t = __ldcg((const float4*)p);
    ulonglong2 r; r.x = packf2(t.x, t.y); r.y = packf2(t.z, t.w);
    return r;
}
__device__ __forceinline__ uint32_t s2u(const void* p) {
    uint32_t a;
    asm("{ .reg .u64 t; cvta.to.shared.u64 t, %1; cvt.u32.u64 %0, t; }"
        : "=r"(a) : "l"(p));
    return a;
}
__device__ __forceinline__ void stc(uint32_t laddr, unsigned rank, float v) {
    uint32_t r;
    asm volatile("mapa.shared::cluster.u32 %0, %1, %2;" : "=r"(r) : "r"(laddr), "r"(rank));
    asm volatile("st.shared::cluster.f32 [%0], %1;" :: "r"(r), "f"(v) : "memory");
}
__device__ __forceinline__ void arrive_rel(uint32_t lmbar, unsigned rank) {
    uint32_t r;
    asm volatile("mapa.shared::cluster.u32 %0, %1, %2;" : "=r"(r) : "r"(lmbar), "r"(rank));
    asm volatile("mbarrier.arrive.release.cluster.shared::cluster.b64 _, [%0];"
                 :: "r"(r) : "memory");
}
__device__ __forceinline__ void waitp(uint32_t mb, unsigned parity) {
    asm volatile(
        "{\n\t.reg .pred P;\n\t"
        "W1_%=:\n\t"
        "mbarrier.try_wait.parity.acquire.cluster.shared::cta.b64 P, [%0], %1, 0x989680;\n\t"
        "@P bra W2_%=;\n\t"
        "bra W1_%=;\n\t"
        "W2_%=:\n\t}"
        :: "r"(mb), "r"(parity) : "memory");
}

// ---------------- M2 = W_A * diag(1/tau) * W_A  (fp32, one-time) ------------
__global__ __launch_bounds__(256) void compute_m2(const float* __restrict__ W_A,
                                                  const float* __restrict__ tau)
{
    __shared__ float ai[HH];
    const int i = blockIdx.x, j = threadIdx.x;
    ai[j] = W_A[i * HH + j] / tau[j];
    __syncthreads();
    float acc = 0.f;
    for (int k = 0; k < HH; k++)
        acc += ai[k] * W_A[k * HH + j];
    g_m2f[i * HH + j] = acc;
}

// ---------------- precompute GEMMs: C[4096,N] = X[4096,128] @ W[N,128]^T + bias (+bias2)
template <int N, int DEST>
__global__ __launch_bounds__(256) void gemm_bias(
    const float* __restrict__ X, const float* __restrict__ W,
    const float* __restrict__ bias, const float* __restrict__ bias2)
{
    constexpr int K = INN;  // 128
    __shared__ float As[32][64];
    __shared__ float Bs[32][64];
    float* C = (DEST == 0) ? g_xg : g_bx;

    const int bm = blockIdx.y * 64, bn = blockIdx.x * 64;
    const int tid = threadIdx.x;
    const int tx = tid & 15, ty = tid >> 4;

    float acc[4][4];
#pragma unroll
    for (int r = 0; r < 4; r++)
#pragma unroll
        for (int c = 0; c < 4; c++) acc[r][c] = 0.f;

    for (int k0 = 0; k0 < K; k0 += 32) {
#pragma unroll
        for (int q = 0; q < 2; q++) {
            int i = tid * 2 + q;
            int row = i >> 3;
            int kc = (i & 7) * 4;
            float4 a = *(const float4*)(X + (size_t)(bm + row) * K + k0 + kc);
            As[kc + 0][row] = a.x; As[kc + 1][row] = a.y;
            As[kc + 2][row] = a.z; As[kc + 3][row] = a.w;
            float4 b = *(const float4*)(W + (size_t)(bn + row) * K + k0 + kc);
            Bs[kc + 0][row] = b.x; Bs[kc + 1][row] = b.y;
            Bs[kc + 2][row] = b.z; Bs[kc + 3][row] = b.w;
        }
        __syncthreads();
#pragma unroll
        for (int kk = 0; kk < 32; kk++) {
            float4 av = *(const float4*)&As[kk][ty * 4];
            float4 bv = *(const float4*)&Bs[kk][tx * 4];
            float ar[4] = {av.x, av.y, av.z, av.w};
            float br[4] = {bv.x, bv.y, bv.z, bv.w};
#pragma unroll
            for (int r = 0; r < 4; r++)
#pragma unroll
                for (int c = 0; c < 4; c++) acc[r][c] += ar[r] * br[c];
        }
        __syncthreads();
    }

    float bc[4];
#pragma unroll
    for (int c = 0; c < 4; c++) {
        bc[c] = bias[bn + tx * 4 + c];
        if (bias2) bc[c] += bias2[bn + tx * 4 + c];
    }
#pragma unroll
    for (int r = 0; r < 4; r++) {
        float4 o;
        o.x = acc[r][0] + bc[0]; o.y = acc[r][1] + bc[1];
        o.z = acc[r][2] + bc[2]; o.w = acc[r][3] + bc[3];
        *(float4*)(C + (size_t)(bm + ty * 4 + r) * N + bn + tx * 4) = o;
    }
}

// ---------------- weight repack (layouts as in R9) --------------------------
__global__ void pack_weights(const float* __restrict__ W_hh,
                             const float* __restrict__ W_A,
                             const float* __restrict__ W_C)
{
    int i = blockIdx.x * blockDim.x + threadIdx.x;
    if (i < G4 * HH) {  // fp16 whh
        int m = i & 7; int u = i >> 3;
        int tid = u & 1023; int cj = u >> 10; int j = cj & 7; int c = cj >> 3;
        int rl = tid >> 2, q = tid & 3;
        int gq = rl >> 6, hl = rl & 63;
        int grow = gq * HH + c * 64 + hl;
        g_whh_h[i] = __float2half(W_hh[grow * HH + q * 64 + j * 8 + m]);
    }
    if (i < HH * HH) {
        int m = i & 3; int r = i >> 2;
        int tid = r & 1023; int cj = r >> 10; int j = cj & 3; int c = cj >> 2;
        int rl = tid >> 4, q = tid & 15;
        int src = (c * 64 + rl) * HH + q * 16 + j * 4 + m;
        g_wa_p[i] = W_A[src];
        g_m2_p[i] = g_m2f[src];
    }
    if (i < OO * HH) {
        int m = i & 3; int r = i >> 2;
        int tid = r & 1023; int cj = r >> 10; int j = cj & 1; int c = cj >> 1;
        int rl = tid >> 5, q = tid & 31;
        g_wc_p[i] = W_C[(c * 32 + rl) * HH + q * 8 + j * 4 + m];
    }
}

// ---------------- sequential fused kernel: 4-CTA cluster per batch ----------
// Exchange ONLY u and h (us/fu recomputed locally); 8 elected release-arrives
// per barrier per step (init count 8) instead of 256.
__global__ __launch_bounds__(1024, 1) __cluster_dims__(4, 1, 1)
void seq_kernel(const float* __restrict__ timespans,  // [B,T]
                const float* __restrict__ tau,        // [H]
                const float* __restrict__ sigma,      // [H]
                const float* __restrict__ b_C,        // [OUT]
                float* __restrict__ out)              // [B,T,OUT]
{
    __shared__ __align__(16) float ex_h[2][HH];    // remote-written
    __shared__ __align__(16) float ex_u[2][HH];    // remote-written
    __shared__ __align__(16) float us_l[HH];       // local: u / tau
    __shared__ __align__(16) float fu_l[HH];       // local: tanh(u / sigma)
    __shared__ __align__(16) float sh_g[256];      // this rank's 256 gate rows
    __shared__ float sh_v1[64], sh_drv[64], sh_v2[64];
    __shared__ float ts_sh[TT];
    __shared__ __align__(8) unsigned long long mbar[2];

    const int tid = threadIdx.x;
    const unsigned c = blockIdx.x & 3;       // cluster rank
    const int b = blockIdx.x >> 2;           // batch

    const float* ts_b = timespans + b * TT;
    if (tid < HH) {
#pragma unroll
        for (int p = 0; p < 2; p++) { ex_h[p][tid] = 0.f; ex_u[p][tid] = 0.f; }
        us_l[tid] = 0.f; fu_l[tid] = 0.f;
    }
    if (tid < TT) ts_sh[tid] = ts_b[tid];
    const uint32_t mb0 = s2u(mbar);
    if (tid == 0) {
        // 8 arrivals per phase: 2 publisher warps x 1 elected lane x 4 CTAs
        asm volatile("mbarrier.init.shared.b64 [%0], %1;" :: "r"(mb0), "r"(8u) : "memory");
        asm volatile("mbarrier.init.shared.b64 [%0], %1;" :: "r"(mb0 + 8), "r"(8u) : "memory");
    }
    __syncthreads();
    asm volatile("barrier.cluster.arrive.aligned;" ::: "memory");
    asm volatile("barrier.cluster.wait.aligned;" ::: "memory");

    // thread roles
    const int rlA = tid >> 2, qA = tid & 3;          // gate rows: 4 lanes/row
    const int gq = rlA >> 6, hl = rlA & 63;
    const int grow = gq * HH + c * 64 + hl;          // global gate row
    const int rlW = tid >> 4, qW = tid & 15;         // W_A/M2 rows: 16 lanes/row
    const int rlC = tid >> 5, qC = tid & 31;         // W_C rows: 32 lanes/row
    const int lane = tid & 31;

    float itau_o = 0.f, u_reg = 0.f, c_reg = 0.f;    // publisher state (tid<64)
    if (tid < 64) itau_o = 1.f / tau[c * 64 + tid];
    float itau_f = 0.f, isig_f = 0.f;                // us/fu recompute (tid<256)
    if (tid < HH) { itau_f = 1.f / tau[tid]; isig_f = 1.f / sigma[tid]; }
    const float bCr = b_C[c * 32 + rlC];

    const ulonglong2* whh16 = (const ulonglong2*)g_whh_h + (c * 8) * 1024 + tid;
    const float* wap = g_wa_p + ((c * 4) * 1024 + tid) * 4;
    const float* m2p = g_m2_p + ((c * 4) * 1024 + tid) * 4;
    const float* wcp = g_wc_p + ((c * 2) * 1024 + tid) * 4;

    const uint32_t a_h[2] = { s2u(ex_h[0]), s2u(ex_h[1]) };
    const uint32_t a_u[2] = { s2u(ex_u[0]), s2u(ex_u[1]) };

    const float* xg_b = g_xg + (size_t)b * TT * G4;
    const float* bx_b = g_bx + (size_t)b * TT * HH;
    float* out_b = out + (size_t)b * TT * OO;

    for (int t = 0; t < TT; t++) {
        const int p = t & 1, pn = p ^ 1;
        const unsigned par = (unsigned)((t >> 1) & 1);
        const float ts = ts_sh[t];

        // prefetch publisher's Bx off the tail critical path
        float bx_r = 0.f;
        if (tid < 64) bx_r = __ldcg(&bx_b[(size_t)t * HH + c * 64 + tid]);

        // ---- Phase A: 256 gate rows, dot(h_prev, W_hh row) fp16, 4 lanes/row
        {
            const ulonglong2* hh = (const ulonglong2*)&ex_h[p][qA * 64];
            ull a0 = 0ull, a1 = 0ull;
#pragma unroll
            for (int j = 0; j < 8; j++) {
                ulonglong2 wv = whh16[j * 1024];   // L1-resident LDG.128 (8 halves)
                ulonglong2 h0 = hh[2 * j];
                ulonglong2 h1 = hh[2 * j + 1];
                a0 = ffma2(a0, h2f2((unsigned)wv.x),         h0.x);
                a1 = ffma2(a1, h2f2((unsigned)(wv.x >> 32)), h0.y);
                a0 = ffma2(a0, h2f2((unsigned)wv.y),         h1.x);
                a1 = ffma2(a1, h2f2((unsigned)(wv.y >> 32)), h1.y);
            }
            float v = hsum2(a0) + hsum2(a1);
            v += __shfl_down_sync(0xffffffffu, v, 2, 4);
            v += __shfl_down_sync(0xffffffffu, v, 1, 4);
            if (qA == 0) sh_g[rlA] = v + __ldcg(&xg_b[(size_t)t * G4 + grow]);
        }

        // ---- Phase A2: v1 = ts*W_A@us, drv = W_A@fu, v2 = ts*M2@us (local)
        {
            const ulonglong2* us2 = (const ulonglong2*)&us_l[qW * 16];
            const ulonglong2* fu2 = (const ulonglong2*)&fu_l[qW * 16];
            ull av = 0ull, ad = 0ull, a2 = 0ull;
#pragma unroll
            for (int j = 0; j < 4; j++) {
                ulonglong2 wv = ldcg16(wap + j * 4096);   // L2-only
                ulonglong2 mv = ldcg16(m2p + j * 4096);   // L2-only
                ulonglong2 uv = us2[j];
                ulonglong2 fv = fu2[j];
                av = ffma2(av, wv.x, uv.x); av = ffma2(av, wv.y, uv.y);
                ad = ffma2(ad, wv.x, fv.x); ad = ffma2(ad, wv.y, fv.y);
                a2 = ffma2(a2, mv.x, uv.x); a2 = ffma2(a2, mv.y, uv.y);
            }
            float v = hsum2(av), d = hsum2(ad), w = hsum2(a2);
#pragma unroll
            for (int o = 8; o >= 1; o >>= 1) {
                v += __shfl_down_sync(0xffffffffu, v, o, 16);
                d += __shfl_down_sync(0xffffffffu, d, o, 16);
                w += __shfl_down_sync(0xffffffffu, w, o, 16);
            }
            if (qW == 0) {
                sh_v1[rlW] = ts * v;
                sh_drv[rlW] = d;
                sh_v2[rlW] = ts * w;     // = A_eff @ v1  (via M2)
            }
        }
        __syncthreads();   // sh_g/sh_v*; also: all local reads of us_l/fu_l/ex[p] done

        // ---- LSTM cell + ODE update (own 64 lanes), publish u & h only ----
        if (tid < 64) {
            float gi = sh_g[tid], gf = sh_g[64 + tid];
            float gg = sh_g[128 + tid], go = sh_g[192 + tid];
            float si = 1.f / (1.f + __expf(-gi));
            float sf = 1.f / (1.f + __expf(-gf));
            float so = 1.f / (1.f + __expf(-go));
            c_reg = sf * c_reg + si * tanhf(gg);
            float bb = so * tanhf(c_reg);

            float un = u_reg + sh_v1[tid] + 0.5f * ts * sh_v2[tid]
                     + ts * (sh_drv[tid] + bx_r) * itau_o + bb;
            u_reg = un;

            const uint32_t off = (unsigned)(c * 64 + tid) * 4;
#pragma unroll
            for (unsigned r = 0; r < 4; r++) {
                stc(a_u[pn] + off, r, un);
                stc(a_h[pn] + off, r, bb);
            }
            __syncwarp(0xffffffffu);
            // elected release-arrive: warpsync gives happens-before for the
            // sibling lanes' stores; the release publishes them cluster-wide.
            if (lane < 4) arrive_rel(mb0 + (unsigned)p * 8, (unsigned)lane);
        }

        waitp(mb0 + (unsigned)p * 8, par);   // full u/h of this step available

        // ---- local recompute of us/fu from exchanged u (exact same math) ---
        if (tid < HH) {
            float uv = ex_u[pn][tid];
            us_l[tid] = uv * itau_f;
            fu_l[tid] = tanhf(uv * isig_f);
        }

        // ---- Phase D: y = u_new @ W_C^T + b_C (own 32 rows, 32 lanes/row) --
        {
            const ulonglong2* uu = (const ulonglong2*)&ex_u[pn][qC * 8];
            ull ay = 0ull;
#pragma unroll
            for (int j = 0; j < 2; j++) {
                ulonglong2 wv = ldcg16(wcp + j * 4096);
                ulonglong2 uv = uu[j];
                ay = ffma2(ay, wv.x, uv.x);
                ay = ffma2(ay, wv.y, uv.y);
            }
            float y = hsum2(ay);
#pragma unroll
            for (int o = 16; o >= 1; o >>= 1)
                y += __shfl_down_sync(0xffffffffu, y, o, 32);
            if (qC == 0) out_b[(size_t)t * OO + c * 32 + rlC] = y + bCr;
        }
        __syncthreads();   // us_l/fu_l visible before next step's Phase A2
    }

    // no CTA may exit while peers' remote stores could still target its SMEM
    asm volatile("barrier.cluster.arrive.aligned;" ::: "memory");
    asm volatile("barrier.cluster.wait.aligned;" ::: "memory");
}

// ---------------- launch ----------------------------------------------------
extern "C" void kernel_launch(void* const* d_in, const int* in_sizes, int n_in,
                              void* d_out, int out_size)
{
    const float* x    = (const float*)d_in[0];   // [32,128,128]
    const float* tsp  = (const float*)d_in[1];   // [32,128]
    const float* tau  = (const float*)d_in[2];   // [256]
    const float* sig  = (const float*)d_in[3];   // [256]
    const float* W_A  = (const float*)d_in[4];   // [256,256]
    const float* W_B  = (const float*)d_in[5];   // [256,128]
    const float* b_B  = (const float*)d_in[6];   // [256]
    const float* W_C  = (const float*)d_in[7];   // [128,256]
    const float* b_C  = (const float*)d_in[8];   // [128]
    const float* W_ih = (const float*)d_in[9];   // [1024,128]
    const float* W_hh = (const float*)d_in[10];  // [1024,256]
    const float* b_ih = (const float*)d_in[11];  // [1024]
    const float* b_hh = (const float*)d_in[12];  // [1024]
    float* out = (float*)d_out;                  // [32,128,128]

    // M2 = W_A * diag(1/tau) * W_A, then repack all weights
    compute_m2<<<HH, HH>>>(W_A, tau);
    pack_weights<<<(G4 * HH + 255) / 256, 256>>>(W_hh, W_A, W_C);

    gemm_bias<G4, 0><<<dim3(G4 / 64, (BB * TT) / 64), 256>>>(x, W_ih, b_ih, b_hh);
    gemm_bias<HH, 1><<<dim3(HH / 64, (BB * TT) / 64), 256>>>(x, W_B, b_B, nullptr);

    // 32 batches x 4-CTA clusters = 128 CTAs
    seq_kernel<<<BB * 4, 1024>>>(tsp, tau, sig, b_C, out);
}

// round 13
// speedup vs baseline: 1.5671x; 1.5570x over previous
#include <cuda_runtime.h>
#include <cuda_fp16.h>
#include <cstdint>

// Sizes (fixed by the problem)
#define BB   32
#define TT   128
#define INN  128
#define HH   256
#define G4   1024   // 4*HH
#define OO   128

// ---------------- scratch (__device__ globals: no runtime allocation) -------
static __device__ __align__(16) float g_xg[BB * TT * G4];   // xg = x@W_ih^T + b_ih + b_hh
static __device__ __align__(16) float g_bx[BB * TT * HH];   // Bx = x@W_B^T + b_B
static __device__ __align__(16) __half g_whh_h[G4 * HH];    // W_hh fp16, 4-way split layout
static __device__ __align__(16) float g_wa_p[HH * HH];      // W_A fp32 repack
static __device__ __align__(16) float g_m2_p[HH * HH];      // M2 = W_A*D*W_A fp32 repack
static __device__ __align__(16) float g_m2f[HH * HH];       // M2 row-major intermediate
static __device__ __align__(16) float g_wc_p[OO * HH];      // W_C fp32 repack

typedef unsigned long long ull;

__device__ __forceinline__ ull ffma2(ull c, ull a, ull b) {
    ull d;
    asm("fma.rn.f32x2 %0, %1, %2, %3;" : "=l"(d) : "l"(a), "l"(b), "l"(c));
    return d;
}
__device__ __forceinline__ float hsum2(ull v) {
    return __uint_as_float((unsigned)(v & 0xffffffffull)) +
           __uint_as_float((unsigned)(v >> 32));
}
__device__ __forceinline__ ull packf2(float x, float y) {
    ull r; asm("mov.b64 %0, {%1, %2};" : "=l"(r) : "f"(x), "f"(y)); return r;
}
__device__ __forceinline__ ull h2f2(unsigned h2bits) {
    __half2 h = *reinterpret_cast<const __half2*>(&h2bits);
    float2 f = __half22float2(h);
    return packf2(f.x, f.y);
}
// 16B L2-only load (protect L1 residency of W_hh)
__device__ __forceinline__ ulonglong2 ldcg16(const void* p) {
    float4 t = __ldcg((const float4*)p);
    ulonglong2 r; r.x = packf2(t.x, t.y); r.y = packf2(t.z, t.w);
    return r;
}
__device__ __forceinline__ uint32_t s2u(const void* p) {
    uint32_t a;
    asm("{ .reg .u64 t; cvta.to.shared.u64 t, %1; cvt.u32.u64 %0, t; }"
        : "=r"(a) : "l"(p));
    return a;
}
__device__ __forceinline__ void stc(uint32_t laddr, unsigned rank, float v) {
    uint32_t r;
    asm volatile("mapa.shared::cluster.u32 %0, %1, %2;" : "=r"(r) : "r"(laddr), "r"(rank));
    asm volatile("st.shared::cluster.f32 [%0], %1;" :: "r"(r), "f"(v) : "memory");
}
__device__ __forceinline__ void arrive_rel(uint32_t lmbar, unsigned rank) {
    uint32_t r;
    asm volatile("mapa.shared::cluster.u32 %0, %1, %2;" : "=r"(r) : "r"(lmbar), "r"(rank));
    asm volatile("mbarrier.arrive.release.cluster.shared::cluster.b64 _, [%0];"
                 :: "r"(r) : "memory");
}
__device__ __forceinline__ void waitp(uint32_t mb, unsigned parity) {
    asm volatile(
        "{\n\t.reg .pred P;\n\t"
        "W1_%=:\n\t"
        "mbarrier.try_wait.parity.acquire.cluster.shared::cta.b64 P, [%0], %1, 0x989680;\n\t"
        "@P bra W2_%=;\n\t"
        "bra W1_%=;\n\t"
        "W2_%=:\n\t}"
        :: "r"(mb), "r"(parity) : "memory");
}

// ---------------- M2 = W_A * diag(1/tau) * W_A  (fp32, one-time) ------------
__global__ __launch_bounds__(256) void compute_m2(const float* __restrict__ W_A,
                                                  const float* __restrict__ tau)
{
    __shared__ float ai[HH];
    const int i = blockIdx.x, j = threadIdx.x;
    ai[j] = W_A[i * HH + j] / tau[j];
    __syncthreads();
    float acc = 0.f;
    for (int k = 0; k < HH; k++)
        acc += ai[k] * W_A[k * HH + j];
    g_m2f[i * HH + j] = acc;
}

// ---------------- precompute GEMMs: C[4096,N] = X[4096,128] @ W[N,128]^T + bias (+bias2)
template <int N, int DEST>
__global__ __launch_bounds__(256) void gemm_bias(
    const float* __restrict__ X, const float* __restrict__ W,
    const float* __restrict__ bias, const float* __restrict__ bias2)
{
    constexpr int K = INN;  // 128
    __shared__ float As[32][64];
    __shared__ float Bs[32][64];
    float* C = (DEST == 0) ? g_xg : g_bx;

    const int bm = blockIdx.y * 64, bn = blockIdx.x * 64;
    const int tid = threadIdx.x;
    const int tx = tid & 15, ty = tid >> 4;

    float acc[4][4];
#pragma unroll
    for (int r = 0; r < 4; r++)
#pragma unroll
        for (int c = 0; c < 4; c++) acc[r][c] = 0.f;

    for (int k0 = 0; k0 < K; k0 += 32) {
#pragma unroll
        for (int q = 0; q < 2; q++) {
            int i = tid * 2 + q;
            int row = i >> 3;
            int kc = (i & 7) * 4;
            float4 a = *(const float4*)(X + (size_t)(bm + row) * K + k0 + kc);
            As[kc + 0][row] = a.x; As[kc + 1][row] = a.y;
            As[kc + 2][row] = a.z; As[kc + 3][row] = a.w;
            float4 b = *(const float4*)(W + (size_t)(bn + row) * K + k0 + kc);
            Bs[kc + 0][row] = b.x; Bs[kc + 1][row] = b.y;
            Bs[kc + 2][row] = b.z; Bs[kc + 3][row] = b.w;
        }
        __syncthreads();
#pragma unroll
        for (int kk = 0; kk < 32; kk++) {
            float4 av = *(const float4*)&As[kk][ty * 4];
            float4 bv = *(const float4*)&Bs[kk][tx * 4];
            float ar[4] = {av.x, av.y, av.z, av.w};
            float br[4] = {bv.x, bv.y, bv.z, bv.w};
#pragma unroll
            for (int r = 0; r < 4; r++)
#pragma unroll
                for (int c = 0; c < 4; c++) acc[r][c] += ar[r] * br[c];
        }
        __syncthreads();
    }

    float bc[4];
#pragma unroll
    for (int c = 0; c < 4; c++) {
        bc[c] = bias[bn + tx * 4 + c];
        if (bias2) bc[c] += bias2[bn + tx * 4 + c];
    }
#pragma unroll
    for (int r = 0; r < 4; r++) {
        float4 o;
        o.x = acc[r][0] + bc[0]; o.y = acc[r][1] + bc[1];
        o.z = acc[r][2] + bc[2]; o.w = acc[r][3] + bc[3];
        *(float4*)(C + (size_t)(bm + ty * 4 + r) * N + bn + tx * 4) = o;
    }
}

// ---------------- weight repack (layouts as in R9) --------------------------
__global__ void pack_weights(const float* __restrict__ W_hh,
                             const float* __restrict__ W_A,
                             const float* __restrict__ W_C)
{
    int i = blockIdx.x * blockDim.x + threadIdx.x;
    if (i < G4 * HH) {  // fp16 whh
        int m = i & 7; int u = i >> 3;
        int tid = u & 1023; int cj = u >> 10; int j = cj & 7; int c = cj >> 3;
        int rl = tid >> 2, q = tid & 3;
        int gq = rl >> 6, hl = rl & 63;
        int grow = gq * HH + c * 64 + hl;
        g_whh_h[i] = __float2half(W_hh[grow * HH + q * 64 + j * 8 + m]);
    }
    if (i < HH * HH) {
        int m = i & 3; int r = i >> 2;
        int tid = r & 1023; int cj = r >> 10; int j = cj & 3; int c = cj >> 2;
        int rl = tid >> 4, q = tid & 15;
        int src = (c * 64 + rl) * HH + q * 16 + j * 4 + m;
        g_wa_p[i] = W_A[src];
        g_m2_p[i] = g_m2f[src];
    }
    if (i < OO * HH) {
        int m = i & 3; int r = i >> 2;
        int tid = r & 1023; int cj = r >> 10; int j = cj & 1; int c = cj >> 1;
        int rl = tid >> 5, q = tid & 31;
        g_wc_p[i] = W_C[(c * 32 + rl) * HH + q * 8 + j * 4 + m];
    }
}

// ---------------- sequential fused kernel: 4-CTA cluster per batch ----------
// EXACT R9 sync structure: ONE __syncthreads + ONE waitp per step, no trailing
// barrier (cross-step warp overlap is load-bearing). M2 slice lives in SMEM.
__global__ __launch_bounds__(1024, 1) __cluster_dims__(4, 1, 1)
void seq_kernel(const float* __restrict__ timespans,  // [B,T]
                const float* __restrict__ tau,        // [H]
                const float* __restrict__ sigma,      // [H]
                const float* __restrict__ b_C,        // [OUT]
                float* __restrict__ out)              // [B,T,OUT]
{
    extern __shared__ __align__(16) float s_m2[];   // 16384 floats = 64 KB

    __shared__ __align__(16) float ex_h[2][HH];
    __shared__ __align__(16) float ex_u[2][HH];
    __shared__ __align__(16) float ex_us[2][HH];   // u / tau
    __shared__ __align__(16) float ex_fu[2][HH];   // tanh(u / sigma)
    __shared__ __align__(16) float sh_g[256];      // this rank's 256 gate rows
    __shared__ float sh_v1[64], sh_drv[64], sh_v2[64];
    __shared__ __align__(8) unsigned long long mbar[2];

    const int tid = threadIdx.x;
    const unsigned c = blockIdx.x & 3;       // cluster rank
    const int b = blockIdx.x >> 2;           // batch

    if (tid < HH) {
#pragma unroll
        for (int p = 0; p < 2; p++) {
            ex_h[p][tid] = 0.f; ex_u[p][tid] = 0.f;
            ex_us[p][tid] = 0.f; ex_fu[p][tid] = 0.f;
        }
    }
    // preload this rank's M2 slice (contiguous 16384 floats) into SMEM
    {
        const float4* src = (const float4*)(g_m2_p + (size_t)c * 16384);
        float4* dst = (float4*)s_m2;
#pragma unroll
        for (int k = 0; k < 4; k++) dst[k * 1024 + tid] = src[k * 1024 + tid];
    }
    const uint32_t mb0 = s2u(mbar);
    if (tid == 0) {
        asm volatile("mbarrier.init.shared.b64 [%0], %1;" :: "r"(mb0), "r"(256u) : "memory");
        asm volatile("mbarrier.init.shared.b64 [%0], %1;" :: "r"(mb0 + 8), "r"(256u) : "memory");
    }
    __syncthreads();
    asm volatile("barrier.cluster.arrive.aligned;" ::: "memory");
    asm volatile("barrier.cluster.wait.aligned;" ::: "memory");

    // thread roles
    const int rlA = tid >> 2, qA = tid & 3;          // gate rows: 4 lanes/row
    const int gq = rlA >> 6, hl = rlA & 63;
    const int grow = gq * HH + c * 64 + hl;          // global gate row
    const int rlW = tid >> 4, qW = tid & 15;         // W_A/M2 rows: 16 lanes/row
    const int rlC = tid >> 5, qC = tid & 31;         // W_C rows: 32 lanes/row

    float itau_o = 0.f, isig_o = 0.f, u_reg = 0.f, c_reg = 0.f;
    if (tid < 64) {
        itau_o = 1.f / tau[c * 64 + tid];
        isig_o = 1.f / sigma[c * 64 + tid];
    }
    const float bCr = b_C[c * 32 + rlC];

    const ulonglong2* whh16 = (const ulonglong2*)g_whh_h + (c * 8) * 1024 + tid;
    const float* wap = g_wa_p + ((c * 4) * 1024 + tid) * 4;
    const ulonglong2* m2s = (const ulonglong2*)s_m2 + tid;   // SMEM, LDS.128
    const float* wcp = g_wc_p + ((c * 2) * 1024 + tid) * 4;

    const uint32_t a_h[2]  = { s2u(ex_h[0]),  s2u(ex_h[1])  };
    const uint32_t a_u[2]  = { s2u(ex_u[0]),  s2u(ex_u[1])  };
    const uint32_t a_us[2] = { s2u(ex_us[0]), s2u(ex_us[1]) };
    const uint32_t a_fu[2] = { s2u(ex_fu[0]), s2u(ex_fu[1]) };

    const float* xg_b = g_xg + (size_t)b * TT * G4;
    const float* bx_b = g_bx + (size_t)b * TT * HH;
    const float* ts_b = timespans + b * TT;
    float* out_b = out + (size_t)b * TT * OO;

    for (int t = 0; t < TT; t++) {
        const int p = t & 1, pn = p ^ 1;
        const unsigned par = (unsigned)((t >> 1) & 1);

        // loop-top prefetch: latency hidden under Phase A's FFMA stream
        const float ts = ts_b[t];
        const float xg_r = __ldcg(&xg_b[(size_t)t * G4 + grow]);
        float bx_r = 0.f;
        if (tid < 64) bx_r = __ldcg(&bx_b[(size_t)t * HH + c * 64 + tid]);

        // ---- Phase A: 256 gate rows, dot(h_prev, W_hh row) fp16, 4 lanes/row
        {
            const ulonglong2* hh = (const ulonglong2*)&ex_h[p][qA * 64];
            ull a0 = 0ull, a1 = 0ull;
#pragma unroll
            for (int j = 0; j < 8; j++) {
                ulonglong2 wv = whh16[j * 1024];   // L1-resident LDG.128 (8 halves)
                ulonglong2 h0 = hh[2 * j];
                ulonglong2 h1 = hh[2 * j + 1];
                a0 = ffma2(a0, h2f2((unsigned)wv.x),         h0.x);
                a1 = ffma2(a1, h2f2((unsigned)(wv.x >> 32)), h0.y);
                a0 = ffma2(a0, h2f2((unsigned)wv.y),         h1.x);
                a1 = ffma2(a1, h2f2((unsigned)(wv.y >> 32)), h1.y);
            }
            float v = hsum2(a0) + hsum2(a1);
            v += __shfl_down_sync(0xffffffffu, v, 2, 4);
            v += __shfl_down_sync(0xffffffffu, v, 1, 4);
            if (qA == 0) sh_g[rlA] = v + xg_r;
        }

        // ---- Phase A2: v1 = ts*W_A@us, drv = W_A@fu, v2 = ts*M2@us (local)
        {
            const ulonglong2* us2 = (const ulonglong2*)&ex_us[p][qW * 16];
            const ulonglong2* fu2 = (const ulonglong2*)&ex_fu[p][qW * 16];
            ull av = 0ull, ad = 0ull, a2 = 0ull;
#pragma unroll
            for (int j = 0; j < 4; j++) {
                ulonglong2 wv = ldcg16(wap + j * 4096);   // L2-only
                ulonglong2 mv = m2s[j * 1024];            // SMEM LDS.128
                ulonglong2 uv = us2[j];
                ulonglong2 fv = fu2[j];
                av = ffma2(av, wv.x, uv.x); av = ffma2(av, wv.y, uv.y);
                ad = ffma2(ad, wv.x, fv.x); ad = ffma2(ad, wv.y, fv.y);
                a2 = ffma2(a2, mv.x, uv.x); a2 = ffma2(a2, mv.y, uv.y);
            }
            float v = hsum2(av), d = hsum2(ad), w = hsum2(a2);
#pragma unroll
            for (int o = 8; o >= 1; o >>= 1) {
                v += __shfl_down_sync(0xffffffffu, v, o, 16);
                d += __shfl_down_sync(0xffffffffu, d, o, 16);
                w += __shfl_down_sync(0xffffffffu, w, o, 16);
            }
            if (qW == 0) {
                sh_v1[rlW] = ts * v;
                sh_drv[rlW] = d;
                sh_v2[rlW] = ts * w;     // = A_eff @ v1  (via M2)
            }
        }
        __syncthreads();   // sh_g / sh_v1 / sh_drv / sh_v2 visible CTA-wide

        // ---- LSTM cell + ODE update (own 64 lanes), publish state ----
        if (tid < 64) {
            float gi = sh_g[tid], gf = sh_g[64 + tid];
            float gg = sh_g[128 + tid], go = sh_g[192 + tid];
            float si = 1.f / (1.f + __expf(-gi));
            float sf = 1.f / (1.f + __expf(-gf));
            float so = 1.f / (1.f + __expf(-go));
            c_reg = sf * c_reg + si * tanhf(gg);
            float bb = so * tanhf(c_reg);

            float un = u_reg + sh_v1[tid] + 0.5f * ts * sh_v2[tid]
                     + ts * (sh_drv[tid] + bx_r) * itau_o + bb;
            u_reg = un;
            float us = un * itau_o;
            float fu = tanhf(un * isig_o);

            const uint32_t off = (unsigned)(c * 64 + tid) * 4;
#pragma unroll
            for (unsigned r = 0; r < 4; r++) {
                stc(a_u[pn] + off, r, un);
                stc(a_us[pn] + off, r, us);
                stc(a_fu[pn] + off, r, fu);
                stc(a_h[pn] + off, r, bb);
            }
#pragma unroll
            for (unsigned r = 0; r < 4; r++) arrive_rel(mb0 + (unsigned)p * 8, r);
        }

        waitp(mb0 + (unsigned)p * 8, par);   // full u/us/fu/h of this step available

        // ---- Phase D: y = u_new @ W_C^T + b_C (own 32 rows, 32 lanes/row) --
        {
            const ulonglong2* uu = (const ulonglong2*)&ex_u[pn][qC * 8];
            ull ay = 0ull;
#pragma unroll
            for (int j = 0; j < 2; j++) {
                ulonglong2 wv = ldcg16(wcp + j * 4096);
                ulonglong2 uv = uu[j];
                ay = ffma2(ay, wv.x, uv.x);
                ay = ffma2(ay, wv.y, uv.y);
            }
            float y = hsum2(ay);
#pragma unroll
            for (int o = 16; o >= 1; o >>= 1)
                y += __shfl_down_sync(0xffffffffu, y, o, 32);
            if (qC == 0) out_b[(size_t)t * OO + c * 32 + rlC] = y + bCr;
        }
        // NO trailing barrier: cross-step warp overlap is the R9 performance
        // property. Next Phase A reads ex[pn] (just waited) and writes sh_g /
        // sh_v* whose prior readers are upstream of this step's BAR chain.
    }

    // no CTA may exit while peers' remote stores could still target its SMEM
    asm volatile("barrier.cluster.arrive.aligned;" ::: "memory");
    asm volatile("barrier.cluster.wait.aligned;" ::: "memory");
}

// ---------------- launch ----------------------------------------------------
extern "C" void kernel_launch(void* const* d_in, const int* in_sizes, int n_in,
                              void* d_out, int out_size)
{
    const float* x    = (const float*)d_in[0];   // [32,128,128]
    const float* tsp  = (const float*)d_in[1];   // [32,128]
    const float* tau  = (const float*)d_in[2];   // [256]
    const float* sig  = (const float*)d_in[3];   // [256]
    const float* W_A  = (const float*)d_in[4];   // [256,256]
    const float* W_B  = (const float*)d_in[5];   // [256,128]
    const float* b_B  = (const float*)d_in[6];   // [256]
    const float* W_C  = (const float*)d_in[7];   // [128,256]
    const float* b_C  = (const float*)d_in[8];   // [128]
    const float* W_ih = (const float*)d_in[9];   // [1024,128]
    const float* W_hh = (const float*)d_in[10];  // [1024,256]
    const float* b_ih = (const float*)d_in[11];  // [1024]
    const float* b_hh = (const float*)d_in[12];  // [1024]
    float* out = (float*)d_out;                  // [32,128,128]

    // allow 64KB dynamic SMEM for the M2 slice (idempotent; not an allocation)
    static bool attr_done = false;
    if (!attr_done) {
        cudaFuncSetAttribute(seq_kernel,
                             cudaFuncAttributeMaxDynamicSharedMemorySize, 65536);
        attr_done = true;
    }

    // M2 = W_A * diag(1/tau) * W_A, then repack all weights
    compute_m2<<<HH, HH>>>(W_A, tau);
    pack_weights<<<(G4 * HH + 255) / 256, 256>>>(W_hh, W_A, W_C);

    gemm_bias<G4, 0><<<dim3(G4 / 64, (BB * TT) / 64), 256>>>(x, W_ih, b_ih, b_hh);
    gemm_bias<HH, 1><<<dim3(HH / 64, (BB * TT) / 64), 256>>>(x, W_B, b_B, nullptr);

    // 32 batches x 4-CTA clusters = 128 CTAs
    seq_kernel<<<BB * 4, 1024, 65536>>>(tsp, tau, sig, b_C, out);
}

// round 14
// speedup vs baseline: 1.8754x; 1.1968x over previous
#include <cuda_runtime.h>
#include <cuda_fp16.h>
#include <cstdint>

// Sizes (fixed by the problem)
#define BB   32
#define TT   128
#define INN  128
#define HH   256
#define G4   1024   // 4*HH
#define OO   128

// ---------------- scratch (__device__ globals: no runtime allocation) -------
static __device__ __align__(16) float g_xg[BB * TT * G4];   // xg = x@W_ih^T + b_ih + b_hh
static __device__ __align__(16) float g_bx[BB * TT * HH];   // Bx = x@W_B^T + b_B
static __device__ __align__(16) __half g_whh_h[G4 * HH];    // W_hh fp16, 512-thread split
static __device__ __align__(16) float g_wa_p[HH * HH];      // W_A fp32 repack (512-thr)
static __device__ __align__(16) float g_m2_p[HH * HH];      // M2 fp32 repack (512-thr)
static __device__ __align__(16) float g_m2f[HH * HH];       // M2 row-major intermediate
static __device__ __align__(16) float g_wc_p[OO * HH];      // W_C fp32 repack (512-thr)

typedef unsigned long long ull;

__device__ __forceinline__ ull ffma2(ull c, ull a, ull b) {
    ull d;
    asm("fma.rn.f32x2 %0, %1, %2, %3;" : "=l"(d) : "l"(a), "l"(b), "l"(c));
    return d;
}
__device__ __forceinline__ float hsum2(ull v) {
    return __uint_as_float((unsigned)(v & 0xffffffffull)) +
           __uint_as_float((unsigned)(v >> 32));
}
__device__ __forceinline__ ull packf2(float x, float y) {
    ull r; asm("mov.b64 %0, {%1, %2};" : "=l"(r) : "f"(x), "f"(y)); return r;
}
__device__ __forceinline__ ull h2f2(unsigned h2bits) {
    __half2 h = *reinterpret_cast<const __half2*>(&h2bits);
    float2 f = __half22float2(h);
    return packf2(f.x, f.y);
}
// 16B L2-only load (protect L1 residency of W_hh)
__device__ __forceinline__ ulonglong2 ldcg16(const void* p) {
    float4 t = __ldcg((const float4*)p);
    ulonglong2 r; r.x = packf2(t.x, t.y); r.y = packf2(t.z, t.w);
    return r;
}
__device__ __forceinline__ uint32_t s2u(const void* p) {
    uint32_t a;
    asm("{ .reg .u64 t; cvta.to.shared.u64 t, %1; cvt.u32.u64 %0, t; }"
        : "=r"(a) : "l"(p));
    return a;
}
__device__ __forceinline__ void stc(uint32_t laddr, unsigned rank, float v) {
    uint32_t r;
    asm volatile("mapa.shared::cluster.u32 %0, %1, %2;" : "=r"(r) : "r"(laddr), "r"(rank));
    asm volatile("st.shared::cluster.f32 [%0], %1;" :: "r"(r), "f"(v) : "memory");
}
__device__ __forceinline__ void arrive_rel(uint32_t lmbar, unsigned rank) {
    uint32_t r;
    asm volatile("mapa.shared::cluster.u32 %0, %1, %2;" : "=r"(r) : "r"(lmbar), "r"(rank));
    asm volatile("mbarrier.arrive.release.cluster.shared::cluster.b64 _, [%0];"
                 :: "r"(r) : "memory");
}
__device__ __forceinline__ void waitp(uint32_t mb, unsigned parity) {
    asm volatile(
        "{\n\t.reg .pred P;\n\t"
        "W1_%=:\n\t"
        "mbarrier.try_wait.parity.acquire.cluster.shared::cta.b64 P, [%0], %1, 0x989680;\n\t"
        "@P bra W2_%=;\n\t"
        "bra W1_%=;\n\t"
        "W2_%=:\n\t}"
        :: "r"(mb), "r"(parity) : "memory");
}

// ---------------- M2 = W_A * diag(1/tau) * W_A  (fp32, one-time) ------------
__global__ __launch_bounds__(256) void compute_m2(const float* __restrict__ W_A,
                                                  const float* __restrict__ tau)
{
    __shared__ float ai[HH];
    const int i = blockIdx.x, j = threadIdx.x;
    ai[j] = W_A[i * HH + j] / tau[j];
    __syncthreads();
    float acc = 0.f;
    for (int k = 0; k < HH; k++)
        acc += ai[k] * W_A[k * HH + j];
    g_m2f[i * HH + j] = acc;
}

// ---------------- precompute GEMMs: C[4096,N] = X[4096,128] @ W[N,128]^T + bias (+bias2)
template <int N, int DEST>
__global__ __launch_bounds__(256) void gemm_bias(
    const float* __restrict__ X, const float* __restrict__ W,
    const float* __restrict__ bias, const float* __restrict__ bias2)
{
    constexpr int K = INN;  // 128
    __shared__ float As[32][64];
    __shared__ float Bs[32][64];
    float* C = (DEST == 0) ? g_xg : g_bx;

    const int bm = blockIdx.y * 64, bn = blockIdx.x * 64;
    const int tid = threadIdx.x;
    const int tx = tid & 15, ty = tid >> 4;

    float acc[4][4];
#pragma unroll
    for (int r = 0; r < 4; r++)
#pragma unroll
        for (int c = 0; c < 4; c++) acc[r][c] = 0.f;

    for (int k0 = 0; k0 < K; k0 += 32) {
#pragma unroll
        for (int q = 0; q < 2; q++) {
            int i = tid * 2 + q;
            int row = i >> 3;
            int kc = (i & 7) * 4;
            float4 a = *(const float4*)(X + (size_t)(bm + row) * K + k0 + kc);
            As[kc + 0][row] = a.x; As[kc + 1][row] = a.y;
            As[kc + 2][row] = a.z; As[kc + 3][row] = a.w;
            float4 b = *(const float4*)(W + (size_t)(bn + row) * K + k0 + kc);
            Bs[kc + 0][row] = b.x; Bs[kc + 1][row] = b.y;
            Bs[kc + 2][row] = b.z; Bs[kc + 3][row] = b.w;
        }
        __syncthreads();
#pragma unroll
        for (int kk = 0; kk < 32; kk++) {
            float4 av = *(const float4*)&As[kk][ty * 4];
            float4 bv = *(const float4*)&Bs[kk][tx * 4];
            float ar[4] = {av.x, av.y, av.z, av.w};
            float br[4] = {bv.x, bv.y, bv.z, bv.w};
#pragma unroll
            for (int r = 0; r < 4; r++)
#pragma unroll
                for (int c = 0; c < 4; c++) acc[r][c] += ar[r] * br[c];
        }
        __syncthreads();
    }

    float bc[4];
#pragma unroll
    for (int c = 0; c < 4; c++) {
        bc[c] = bias[bn + tx * 4 + c];
        if (bias2) bc[c] += bias2[bn + tx * 4 + c];
    }
#pragma unroll
    for (int r = 0; r < 4; r++) {
        float4 o;
        o.x = acc[r][0] + bc[0]; o.y = acc[r][1] + bc[1];
        o.z = acc[r][2] + bc[2]; o.w = acc[r][3] + bc[3];
        *(float4*)(C + (size_t)(bm + ty * 4 + r) * N + bn + tx * 4) = o;
    }
}

// ---------------- weight repack for the 512-thread layout -------------------
// whh (fp16), kernel access: u2 idx = (c*16 + j)*512 + tid, j in [0,16)
//   rl=tid>>1, qA=tid&1, gq=rl>>6, hl=rl&63, grow=gq*256+c*64+hl
//   halves m=0..7 map to k = qA*128 + j*8 + m
// wa/m2 (fp32), kernel access: u2 idx = (c*8 + j)*512 + tid, j in [0,8)
//   row = c*64 + (tid>>3), k = (tid&7)*32 + j*4 + m
// wc (fp32), kernel access: u2 idx = (c*4 + j)*512 + tid, j in [0,4)
//   row = c*32 + (tid>>4), k = (tid&15)*16 + j*4 + m
__global__ void pack_weights(const float* __restrict__ W_hh,
                             const float* __restrict__ W_A,
                             const float* __restrict__ W_C)
{
    int i = blockIdx.x * blockDim.x + threadIdx.x;
    if (i < G4 * HH) {  // fp16 whh, half index
        int m = i & 7; int u = i >> 3;
        int tid = u & 511; int cj = u >> 9; int j = cj & 15; int c = cj >> 4;
        int rl = tid >> 1, qA = tid & 1;
        int gq = rl >> 6, hl = rl & 63;
        int grow = gq * HH + c * 64 + hl;
        g_whh_h[i] = __float2half(W_hh[grow * HH + qA * 128 + j * 8 + m]);
    }
    if (i < HH * HH) {  // fp32 wa / m2, float index
        int m = i & 3; int r = i >> 2;
        int tid = r & 511; int cj = r >> 9; int j = cj & 7; int c = cj >> 3;
        int row = c * 64 + (tid >> 3);
        int k = (tid & 7) * 32 + j * 4 + m;
        int src = row * HH + k;
        g_wa_p[i] = W_A[src];
        g_m2_p[i] = g_m2f[src];
    }
    if (i < OO * HH) {  // fp32 wc, float index
        int m = i & 3; int r = i >> 2;
        int tid = r & 511; int cj = r >> 9; int j = cj & 3; int c = cj >> 2;
        int row = c * 32 + (tid >> 4);
        int k = (tid & 15) * 16 + j * 4 + m;
        g_wc_p[i] = W_C[row * HH + k];
    }
}

// ---------------- sequential fused kernel: 4-CTA cluster per batch ----------
// 512 threads x 128 regs. Loop-invariant W_A / M2 / W_C live in REGISTERS;
// only fp16 W_hh streams from L1. Sync skeleton identical to R9/R13:
// ONE __syncthreads + ONE waitp per step, no trailing barrier.
__global__ __launch_bounds__(512, 1) __cluster_dims__(4, 1, 1)
void seq_kernel(const float* __restrict__ timespans,  // [B,T]
                const float* __restrict__ tau,        // [H]
                const float* __restrict__ sigma,      // [H]
                const float* __restrict__ b_C,        // [OUT]
                float* __restrict__ out)              // [B,T,OUT]
{
    __shared__ __align__(16) float ex_h[2][HH];
    __shared__ __align__(16) float ex_u[2][HH];
    __shared__ __align__(16) float ex_us[2][HH];   // u / tau
    __shared__ __align__(16) float ex_fu[2][HH];   // tanh(u / sigma)
    __shared__ __align__(16) float sh_g[256];      // this rank's 256 gate rows
    __shared__ float sh_v1[64], sh_drv[64], sh_v2[64];
    __shared__ __align__(8) unsigned long long mbar[2];

    const int tid = threadIdx.x;
    const unsigned c = blockIdx.x & 3;       // cluster rank
    const int b = blockIdx.x >> 2;           // batch

    if (tid < HH) {
#pragma unroll
        for (int p = 0; p < 2; p++) {
            ex_h[p][tid] = 0.f; ex_u[p][tid] = 0.f;
            ex_us[p][tid] = 0.f; ex_fu[p][tid] = 0.f;
        }
    }
    const uint32_t mb0 = s2u(mbar);
    if (tid == 0) {
        asm volatile("mbarrier.init.shared.b64 [%0], %1;" :: "r"(mb0), "r"(256u) : "memory");
        asm volatile("mbarrier.init.shared.b64 [%0], %1;" :: "r"(mb0 + 8), "r"(256u) : "memory");
    }
    __syncthreads();
    asm volatile("barrier.cluster.arrive.aligned;" ::: "memory");
    asm volatile("barrier.cluster.wait.aligned;" ::: "memory");

    // thread roles (512 threads)
    const int rlA = tid >> 1, qA = tid & 1;          // gate rows: 2 lanes/row
    const int gq = rlA >> 6, hl = rlA & 63;
    const int grow = gq * HH + c * 64 + hl;          // global gate row
    const int rlW = tid >> 3, qW = tid & 7;          // W_A/M2 rows: 8 lanes/row
    const int rlC = tid >> 4, qC = tid & 15;         // W_C rows: 16 lanes/row

    float itau_o = 0.f, isig_o = 0.f, u_reg = 0.f, c_reg = 0.f;
    if (tid < 64) {
        itau_o = 1.f / tau[c * 64 + tid];
        isig_o = 1.f / sigma[c * 64 + tid];
    }
    const float bCr = b_C[c * 32 + rlC];

    // ---- loop-invariant weights -> registers (one-time L2 reads) ----
    ulonglong2 wa_r[8], m2_r[8], wc_r[4];
#pragma unroll
    for (int j = 0; j < 8; j++) {
        wa_r[j] = ldcg16(g_wa_p + (((unsigned)c * 8 + j) * 512 + tid) * 4);
        m2_r[j] = ldcg16(g_m2_p + (((unsigned)c * 8 + j) * 512 + tid) * 4);
    }
#pragma unroll
    for (int j = 0; j < 4; j++)
        wc_r[j] = ldcg16(g_wc_p + (((unsigned)c * 4 + j) * 512 + tid) * 4);

    const ulonglong2* whh16 = (const ulonglong2*)g_whh_h + (c * 16) * 512 + tid;

    const uint32_t a_h[2]  = { s2u(ex_h[0]),  s2u(ex_h[1])  };
    const uint32_t a_u[2]  = { s2u(ex_u[0]),  s2u(ex_u[1])  };
    const uint32_t a_us[2] = { s2u(ex_us[0]), s2u(ex_us[1]) };
    const uint32_t a_fu[2] = { s2u(ex_fu[0]), s2u(ex_fu[1]) };

    const float* xg_b = g_xg + (size_t)b * TT * G4;
    const float* bx_b = g_bx + (size_t)b * TT * HH;
    const float* ts_b = timespans + b * TT;
    float* out_b = out + (size_t)b * TT * OO;

    for (int t = 0; t < TT; t++) {
        const int p = t & 1, pn = p ^ 1;
        const unsigned par = (unsigned)((t >> 1) & 1);

        // loop-top prefetch (hidden under Phase A)
        const float ts = ts_b[t];
        const float xg_r = __ldcg(&xg_b[(size_t)t * G4 + grow]);
        float bx_r = 0.f;
        if (tid < 64) bx_r = __ldcg(&bx_b[(size_t)t * HH + c * 64 + tid]);

        // ---- Phase A: 256 gate rows, 2 lanes/row, k-range 128 each --------
        {
            const ulonglong2* hh = (const ulonglong2*)&ex_h[p][qA * 128];
            ull a0 = 0ull, a1 = 0ull;
#pragma unroll
            for (int j = 0; j < 16; j++) {
                ulonglong2 wv = whh16[j * 512];   // L1-resident LDG.128 (8 halves)
                ulonglong2 h0 = hh[2 * j];
                ulonglong2 h1 = hh[2 * j + 1];
                a0 = ffma2(a0, h2f2((unsigned)wv.x),         h0.x);
                a1 = ffma2(a1, h2f2((unsigned)(wv.x >> 32)), h0.y);
                a0 = ffma2(a0, h2f2((unsigned)wv.y),         h1.x);
                a1 = ffma2(a1, h2f2((unsigned)(wv.y >> 32)), h1.y);
            }
            float v = hsum2(a0) + hsum2(a1);
            v += __shfl_down_sync(0xffffffffu, v, 1, 2);
            if (qA == 0) sh_g[rlA] = v + xg_r;
        }

        // ---- Phase A2: v1 = ts*W_A@us, drv = W_A@fu, v2 = ts*M2@us --------
        // weights in REGISTERS; activations via LDS
        {
            const ulonglong2* us2 = (const ulonglong2*)&ex_us[p][qW * 32];
            const ulonglong2* fu2 = (const ulonglong2*)&ex_fu[p][qW * 32];
            ull av = 0ull, ad = 0ull, a2 = 0ull;
#pragma unroll
            for (int j = 0; j < 8; j++) {
                ulonglong2 uv = us2[j];
                ulonglong2 fv = fu2[j];
                av = ffma2(av, wa_r[j].x, uv.x); av = ffma2(av, wa_r[j].y, uv.y);
                ad = ffma2(ad, wa_r[j].x, fv.x); ad = ffma2(ad, wa_r[j].y, fv.y);
                a2 = ffma2(a2, m2_r[j].x, uv.x); a2 = ffma2(a2, m2_r[j].y, uv.y);
            }
            float v = hsum2(av), d = hsum2(ad), w = hsum2(a2);
#pragma unroll
            for (int o = 4; o >= 1; o >>= 1) {
                v += __shfl_down_sync(0xffffffffu, v, o, 8);
                d += __shfl_down_sync(0xffffffffu, d, o, 8);
                w += __shfl_down_sync(0xffffffffu, w, o, 8);
            }
            if (qW == 0) {
                sh_v1[rlW] = ts * v;
                sh_drv[rlW] = d;
                sh_v2[rlW] = ts * w;     // = A_eff @ v1  (via M2)
            }
        }
        __syncthreads();   // sh_g / sh_v1 / sh_drv / sh_v2 visible CTA-wide

        // ---- LSTM cell + ODE update (own 64 lanes), publish state ----
        if (tid < 64) {
            float gi = sh_g[tid], gf = sh_g[64 + tid];
            float gg = sh_g[128 + tid], go = sh_g[192 + tid];
            float si = 1.f / (1.f + __expf(-gi));
            float sf = 1.f / (1.f + __expf(-gf));
            float so = 1.f / (1.f + __expf(-go));
            c_reg = sf * c_reg + si * tanhf(gg);
            float bb = so * tanhf(c_reg);

            float un = u_reg + sh_v1[tid] + 0.5f * ts * sh_v2[tid]
                     + ts * (sh_drv[tid] + bx_r) * itau_o + bb;
            u_reg = un;
            float us = un * itau_o;
            float fu = tanhf(un * isig_o);

            const uint32_t off = (unsigned)(c * 64 + tid) * 4;
#pragma unroll
            for (unsigned r = 0; r < 4; r++) {
                stc(a_u[pn] + off, r, un);
                stc(a_us[pn] + off, r, us);
                stc(a_fu[pn] + off, r, fu);
                stc(a_h[pn] + off, r, bb);
            }
#pragma unroll
            for (unsigned r = 0; r < 4; r++) arrive_rel(mb0 + (unsigned)p * 8, r);
        }

        waitp(mb0 + (unsigned)p * 8, par);   // full u/us/fu/h of this step available

        // ---- Phase D: y = u_new @ W_C^T + b_C (32 rows, 16 lanes/row) -----
        {
            const ulonglong2* uu = (const ulonglong2*)&ex_u[pn][qC * 16];
            ull ay = 0ull;
#pragma unroll
            for (int j = 0; j < 4; j++) {
                ulonglong2 uv = uu[j];
                ay = ffma2(ay, wc_r[j].x, uv.x);
                ay = ffma2(ay, wc_r[j].y, uv.y);
            }
            float y = hsum2(ay);
#pragma unroll
            for (int o = 8; o >= 1; o >>= 1)
                y += __shfl_down_sync(0xffffffffu, y, o, 16);
            if (qC == 0) out_b[(size_t)t * OO + c * 32 + rlC] = y + bCr;
        }
        // NO trailing barrier: cross-step warp overlap is load-bearing (R10/R11
        // both regressed 700us when any extra per-step convergence was added).
    }

    // no CTA may exit while peers' remote stores could still target its SMEM
    asm volatile("barrier.cluster.arrive.aligned;" ::: "memory");
    asm volatile("barrier.cluster.wait.aligned;" ::: "memory");
}

// ---------------- launch ----------------------------------------------------
extern "C" void kernel_launch(void* const* d_in, const int* in_sizes, int n_in,
                              void* d_out, int out_size)
{
    const float* x    = (const float*)d_in[0];   // [32,128,128]
    const float* tsp  = (const float*)d_in[1];   // [32,128]
    const float* tau  = (const float*)d_in[2];   // [256]
    const float* sig  = (const float*)d_in[3];   // [256]
    const float* W_A  = (const float*)d_in[4];   // [256,256]
    const float* W_B  = (const float*)d_in[5];   // [256,128]
    const float* b_B  = (const float*)d_in[6];   // [256]
    const float* W_C  = (const float*)d_in[7];   // [128,256]
    const float* b_C  = (const float*)d_in[8];   // [128]
    const float* W_ih = (const float*)d_in[9];   // [1024,128]
    const float* W_hh = (const float*)d_in[10];  // [1024,256]
    const float* b_ih = (const float*)d_in[11];  // [1024]
    const float* b_hh = (const float*)d_in[12];  // [1024]
    float* out = (float*)d_out;                  // [32,128,128]

    // M2 = W_A * diag(1/tau) * W_A, then repack all weights
    compute_m2<<<HH, HH>>>(W_A, tau);
    pack_weights<<<(G4 * HH + 255) / 256, 256>>>(W_hh, W_A, W_C);

    gemm_bias<G4, 0><<<dim3(G4 / 64, (BB * TT) / 64), 256>>>(x, W_ih, b_ih, b_hh);
    gemm_bias<HH, 1><<<dim3(HH / 64, (BB * TT) / 64), 256>>>(x, W_B, b_B, nullptr);

    // 32 batches x 4-CTA clusters = 128 CTAs, 512 threads each
    seq_kernel<<<BB * 4, 512>>>(tsp, tau, sig, b_C, out);
}